// round 6
// baseline (speedup 1.0000x reference)
#include <cuda_runtime.h>
#include <cuda_bf16.h>

#define NMAX 100000
#define EMAX 1600000
#define HDIM 64
#define STRIDE 96   // ELL row stride; max Poisson(16) degree over 100K nodes ~ 45

typedef unsigned long long ull;

// ---------------- scratch (device globals; no allocation allowed) -----------
__device__ __align__(256) int   g_degi[NMAX];           // degree (atomic counter)
__device__ __align__(256) int   g_ell[NMAX * STRIDE];   // neighbor ids (ELL)
__device__ __align__(256) float g_pre1[NMAX * HDIM];    // layer-1 pre-BN output
__device__ __align__(256) float g_pre2[NMAX * HDIM];    // layer-2 pre-BN output
__device__ float g_colsum[HDIM];
__device__ float g_colsq[HDIM];
__device__ float g_scale[HDIM];
__device__ float g_shift[HDIM];
__device__ int   g_is64;

// packed fp32x2 FMA (Blackwell): acc = a*b + acc, two MACs per instruction
#define FMA2(acc, a, b) \
    asm("fma.rn.f32x2 %0, %1, %2, %0;" : "+l"(acc) : "l"(a), "l"(b))

__device__ __forceinline__ float2 unpack2(ull v) {
    float2 r;
    asm("mov.b64 {%0, %1}, %2;" : "=f"(r.x), "=f"(r.y) : "l"(v));
    return r;
}

// ---------------- edge-index dtype detection --------------------------------
// jnp.int64 without jax x64 silently becomes int32. Node ids < 1e5, so under
// an int64 layout every odd 32-bit word is zero.
__global__ void detect_kernel(const unsigned int* __restrict__ ei32) {
    __shared__ unsigned int acc;
    if (threadIdx.x == 0) acc = 0u;
    __syncthreads();
    unsigned int v = 0u;
    for (int i = threadIdx.x; i < 4096; i += blockDim.x) v |= ei32[2 * i + 1];
    atomicOr(&acc, v);
    __syncthreads();
    if (threadIdx.x == 0) g_is64 = (acc == 0u) ? 1 : 0;
}

__device__ __forceinline__ long long load_idx(const void* ei, long long pos, int is64) {
    if (is64) return ((const long long*)ei)[pos];
    return (long long)((const int*)ei)[pos];
}

// ---------------- zero degree + BN stats ------------------------------------
__global__ void zero_kernel(int n) {
    int i = blockIdx.x * blockDim.x + threadIdx.x;
    if (i < n) g_degi[i] = 0;
    if (i < HDIM) { g_colsum[i] = 0.f; g_colsq[i] = 0.f; }
}

// ---------------- ELL fill (also produces degree) ---------------------------
__global__ void __launch_bounds__(256) fill_kernel(const void* __restrict__ ei,
                                                   long long E) {
    long long e = (long long)blockIdx.x * blockDim.x + threadIdx.x;
    if (e >= E) return;
    int is64 = g_is64;
    int s = (int)load_idx(ei, e, is64);
    int d = (int)load_idx(ei, E + e, is64);
    int slot = atomicAdd(&g_degi[d], 1);
    if (slot < STRIDE) g_ell[d * STRIDE + slot] = s;
}

// ---------------- fused layer ------------------------------------------------
// ELL gather-mean (+ optional on-the-fly BN+relu of the input) + stacked GEMV
// [inv*agg | root] @ [Wl; Wr]^T + bias, + BN stat accumulation.
// 256 threads (8 warps); each warp processes 4 nodes per iteration.
// Input (xin) and output (yout) MUST be distinct buffers (no aliasing: the
// gather reads arbitrary rows of xin while yout rows are being written).
__global__ void __launch_bounds__(256) layer_kernel(
    const float* __restrict__ xin, float* __restrict__ yout,
    const float* __restrict__ Wl, const float* __restrict__ bl,
    const float* __restrict__ Wr, int apply_norm, int n)
{
    __shared__ __align__(16) ull   sW[2][64][32];        // 32 KB
    __shared__ __align__(16) float shV[8][4][2 * HDIM];  // 16 KB

    int tid = threadIdx.x;
    for (int i = tid; i < 4096; i += 256) {
        int m = i >> 11, kp = (i >> 5) & 63, ln = i & 31;
        int row = 2 * ln + m;
        ull w = (kp < 32) ? ((const ull*)Wl)[row * 32 + kp]
                          : ((const ull*)Wr)[row * 32 + (kp - 32)];
        sW[m][kp][ln] = w;
    }
    __syncthreads();

    int warp = tid >> 5, lane = tid & 31;
    int j0 = 2 * lane;
    float b0 = bl[j0], b1 = bl[j0 + 1];
    float sc0 = 1.f, sc1 = 1.f, sh0 = 0.f, sh1 = 0.f;
    if (apply_norm) {
        sc0 = g_scale[j0]; sc1 = g_scale[j0 + 1];
        sh0 = g_shift[j0]; sh1 = g_shift[j0 + 1];
    }
    float s0 = 0.f, s1 = 0.f, q0 = 0.f, q1 = 0.f;

    for (long long grp = (long long)blockIdx.x * 8 + warp; grp * 4 < n;
         grp += (long long)gridDim.x * 8) {
        long long node0 = grp * 4;
        int nvalid = (n - node0 >= 4) ? 4 : (int)(n - node0);

        // ---- gather (+optional norm) into smem staging ----
        for (int nd = 0; nd < nvalid; nd++) {
            long long node = node0 + nd;
            int deg = g_degi[node];
            int dcap = min(deg, STRIDE);
            const int* nb = g_ell + node * STRIDE;
            float ax = 0.f, ay = 0.f;
            for (int base = 0; base < dcap; base += 32) {
                int cnt = min(32, dcap - base);
                int myid = nb[base + lane];   // in-bounds even past cnt
                int j = 0;
                for (; j + 4 <= cnt; j += 4) {
                    int i0 = __shfl_sync(0xffffffffu, myid, j);
                    int i1 = __shfl_sync(0xffffffffu, myid, j + 1);
                    int i2 = __shfl_sync(0xffffffffu, myid, j + 2);
                    int i3 = __shfl_sync(0xffffffffu, myid, j + 3);
                    float2 v0 = __ldg((const float2*)(xin + (long long)i0 * HDIM) + lane);
                    float2 v1 = __ldg((const float2*)(xin + (long long)i1 * HDIM) + lane);
                    float2 v2 = __ldg((const float2*)(xin + (long long)i2 * HDIM) + lane);
                    float2 v3 = __ldg((const float2*)(xin + (long long)i3 * HDIM) + lane);
                    if (apply_norm) {
                        v0.x = fmaxf(fmaf(v0.x, sc0, sh0), 0.f);
                        v0.y = fmaxf(fmaf(v0.y, sc1, sh1), 0.f);
                        v1.x = fmaxf(fmaf(v1.x, sc0, sh0), 0.f);
                        v1.y = fmaxf(fmaf(v1.y, sc1, sh1), 0.f);
                        v2.x = fmaxf(fmaf(v2.x, sc0, sh0), 0.f);
                        v2.y = fmaxf(fmaf(v2.y, sc1, sh1), 0.f);
                        v3.x = fmaxf(fmaf(v3.x, sc0, sh0), 0.f);
                        v3.y = fmaxf(fmaf(v3.y, sc1, sh1), 0.f);
                    }
                    ax += (v0.x + v1.x) + (v2.x + v3.x);
                    ay += (v0.y + v1.y) + (v2.y + v3.y);
                }
                for (; j < cnt; j++) {
                    int ii = __shfl_sync(0xffffffffu, myid, j);
                    float2 v = __ldg((const float2*)(xin + (long long)ii * HDIM) + lane);
                    if (apply_norm) {
                        v.x = fmaxf(fmaf(v.x, sc0, sh0), 0.f);
                        v.y = fmaxf(fmaf(v.y, sc1, sh1), 0.f);
                    }
                    ax += v.x; ay += v.y;
                }
            }
            float inv = 1.0f / fmaxf((float)deg, 1.0f);
            ax *= inv; ay *= inv;
            float2 xv = __ldg((const float2*)(xin + node * HDIM) + lane);
            if (apply_norm) {
                xv.x = fmaxf(fmaf(xv.x, sc0, sh0), 0.f);
                xv.y = fmaxf(fmaf(xv.y, sc1, sh1), 0.f);
            }
            shV[warp][nd][j0] = ax;
            shV[warp][nd][j0 + 1] = ay;
            shV[warp][nd][HDIM + j0] = xv.x;
            shV[warp][nd][HDIM + j0 + 1] = xv.y;
        }
        __syncwarp();

        // ---- stacked GEMV: K=128, packed f32x2, 4 nodes share weight reads ----
        ull aO0[4] = {0, 0, 0, 0}, aO1[4] = {0, 0, 0, 0};
#pragma unroll 8
        for (int kp = 0; kp < 64; kp++) {
            ull w0 = sW[0][kp][lane];
            ull w1 = sW[1][kp][lane];
#pragma unroll
            for (int nd = 0; nd < 4; nd++) {
                ull v = *(const ull*)&shV[warp][nd][2 * kp];
                FMA2(aO0[nd], v, w0);
                FMA2(aO1[nd], v, w1);
            }
        }
#pragma unroll
        for (int nd = 0; nd < 4; nd++) {
            if (nd < nvalid) {
                float2 o0p = unpack2(aO0[nd]);
                float2 o1p = unpack2(aO1[nd]);
                float o0 = o0p.x + o0p.y + b0;
                float o1 = o1p.x + o1p.y + b1;
                long long node = node0 + nd;
                ((float2*)(yout + node * HDIM))[lane] = make_float2(o0, o1);
                s0 += o0; s1 += o1; q0 += o0 * o0; q1 += o1 * o1;
            }
        }
        __syncwarp();
    }
    atomicAdd(&g_colsum[j0],     s0);
    atomicAdd(&g_colsum[j0 + 1], s1);
    atomicAdd(&g_colsq[j0],      q0);
    atomicAdd(&g_colsq[j0 + 1],  q1);
}

// ---------------- BN stats -> scale/shift (and reset stats) ------------------
__global__ void bn_kernel(const float* __restrict__ gamma,
                          const float* __restrict__ beta, float fn) {
    int j = threadIdx.x;
    float mean = g_colsum[j] / fn;
    float var = g_colsq[j] / fn - mean * mean;
    float sc = gamma[j] * rsqrtf(var + 1e-5f);
    g_scale[j] = sc;
    g_shift[j] = beta[j] - mean * sc;
    g_colsum[j] = 0.f;   // ready for next layer's accumulation
    g_colsq[j]  = 0.f;
}

// ---------------- layer-2 normalize + relu + decoder (fused) -----------------
// Reads g_pre2; writes logits to d_out[0 .. N*C) and h to d_out[N*C ..].
__global__ void __launch_bounds__(256) final_kernel(const float* __restrict__ Wd,
                                                    const float* __restrict__ bd,
                                                    float* __restrict__ out,
                                                    int n, int C) {
    __shared__ float WdT[HDIM * 48];   // padded stride 48, zero-filled
    __shared__ float shh[8][HDIM];
    __shared__ float sbd[48];
    int tid = threadIdx.x;
    for (int i = tid; i < HDIM * 48; i += 256) WdT[i] = 0.f;
    if (tid < 48) sbd[tid] = (tid < C) ? bd[tid] : 0.f;
    __syncthreads();
    for (int i = tid; i < C * HDIM; i += 256) {
        int c = i >> 6, k = i & 63;
        WdT[k * 48 + c] = Wd[i];
    }
    __syncthreads();

    int warp = tid >> 5, lane = tid & 31;
    int j0 = 2 * lane;
    float sc0 = g_scale[j0], sc1 = g_scale[j0 + 1];
    float sh0 = g_shift[j0], sh1 = g_shift[j0 + 1];
    float* hout = out + (long long)n * C;

    for (long long node = (long long)blockIdx.x * 8 + warp; node < n;
         node += (long long)gridDim.x * 8) {
        float2 p = ((const float2*)(g_pre2 + node * HDIM))[lane];
        float h0 = fmaxf(fmaf(p.x, sc0, sh0), 0.f);
        float h1 = fmaxf(fmaf(p.y, sc1, sh1), 0.f);
        ((float2*)(hout + node * HDIM))[lane] = make_float2(h0, h1);
        shh[warp][j0] = h0; shh[warp][j0 + 1] = h1;
        __syncwarp();
        float a0 = 0.f, a1 = 0.f;
#pragma unroll
        for (int k = 0; k < HDIM; k++) {
            float hv = shh[warp][k];
            a0 = fmaf(hv, WdT[k * 48 + lane], a0);
            a1 = fmaf(hv, WdT[k * 48 + lane + 32], a1);
        }
        out[node * C + lane] = a0 + sbd[lane];
        if (lane + 32 < C) out[node * C + lane + 32] = a1 + sbd[lane + 32];
        __syncwarp();
    }
}

// ---------------- launch -----------------------------------------------------
extern "C" void kernel_launch(void* const* d_in, const int* in_sizes, int n_in,
                              void* d_out, int out_size) {
    const float* x   = (const float*)d_in[0];
    const void*  ei  = d_in[1];
    const float* W1l = (const float*)d_in[2];
    const float* b1l = (const float*)d_in[3];
    const float* W1r = (const float*)d_in[4];
    const float* g1  = (const float*)d_in[5];
    const float* be1 = (const float*)d_in[6];
    const float* W2l = (const float*)d_in[7];
    const float* b2l = (const float*)d_in[8];
    const float* W2r = (const float*)d_in[9];
    const float* g2  = (const float*)d_in[10];
    const float* be2 = (const float*)d_in[11];
    const float* Wd  = (const float*)d_in[12];
    const float* bd  = (const float*)d_in[13];
    float* out = (float*)d_out;

    int n = in_sizes[0] / HDIM;               // 100000
    long long E = (long long)in_sizes[1] / 2; // 1600000
    int C = in_sizes[12] / HDIM;              // 40

    float* p_pre1 = nullptr;
    float* p_pre2 = nullptr;
    cudaGetSymbolAddress((void**)&p_pre1, g_pre1);
    cudaGetSymbolAddress((void**)&p_pre2, g_pre2);

    int eb = (int)((E + 255) / 256);
    const int LAYER_GRID = 592;   // 4 blocks/SM

    // launch order matters for profiling: layer_kernel (L1) is the 4th launch
    detect_kernel<<<1, 256>>>((const unsigned int*)ei);                    // 1
    zero_kernel<<<(n + 255) / 256, 256>>>(n);                              // 2
    fill_kernel<<<eb, 256>>>(ei, E);                                       // 3

    layer_kernel<<<LAYER_GRID, 256>>>(x, p_pre1, W1l, b1l, W1r, 0, n);     // 4 (profiled)
    bn_kernel<<<1, HDIM>>>(g1, be1, (float)n);                             // 5

    layer_kernel<<<LAYER_GRID, 256>>>(p_pre1, p_pre2, W2l, b2l, W2r, 1, n);// 6
    bn_kernel<<<1, HDIM>>>(g2, be2, (float)n);                             // 7

    final_kernel<<<LAYER_GRID, 256>>>(Wd, bd, out, n, C);                  // 8
}